// round 7
// baseline (speedup 1.0000x reference)
#include <cuda_runtime.h>
#include <math.h>

#define NLOC 50000
#define BB 4
#define TT 16
#define NFEAT 4
#define NTOT (BB*NLOC)   /* 200000 */
#define H 32
#define EMAX 1800000
#define FULL 0xffffffffu

// ---- device scratch (no allocation allowed) ----
__device__ float g_z1[(size_t)NTOT*H];
__device__ float g_z2[(size_t)NTOT*H];
__device__ float g_s1[NTOT], g_d1[NTOT];
__device__ float g_s2[NTOT], g_d2[NTOT];
__device__ int   g_deg[NTOT];
__device__ int   g_rowptr[NTOT+1];
__device__ int   g_fill[NTOT];
__device__ int   g_col[EMAX];

__device__ __forceinline__ float warp_sum(float v){
  #pragma unroll
  for(int o=16;o;o>>=1) v += __shfl_xor_sync(FULL, v, o);
  return v;
}
__device__ __forceinline__ float sigm(float x){ return 1.f/(1.f+expf(-x)); }
__device__ __forceinline__ float eluf(float x){ return x>0.f ? x : expm1f(x); }
__device__ __forceinline__ float lrelu(float x){ return x>=0.f ? x : 0.01f*x; }

// ======================= CSR build =======================
__global__ void k_zero(){
  int n = blockIdx.x*256 + threadIdx.x;
  if(n<NTOT) g_deg[n]=0;
}
__global__ void k_hist(const int* __restrict__ adj, int E){
  int e = blockIdx.x*256 + threadIdx.x;
  if(e<E) atomicAdd(&g_deg[__ldg(&adj[E+e])], 1);
}
// single-block exclusive scan over 200K degrees (1024 thr, chunked)
__global__ void k_scan(){
  __shared__ int sp[1024];
  const int T = 1024;
  const int chunk = (NTOT + T - 1)/T;
  int t = threadIdx.x;
  int lo = t*chunk, hi = min(lo+chunk, NTOT);
  int s = 0;
  for(int i=lo;i<hi;i++) s += g_deg[i];
  sp[t]=s; __syncthreads();
  // inclusive Hillis-Steele
  for(int off=1;off<T;off<<=1){
    int v = (t>=off)? sp[t-off] : 0;
    __syncthreads();
    sp[t] += v;
    __syncthreads();
  }
  int run = sp[t] - s;   // exclusive prefix of this chunk
  for(int i=lo;i<hi;i++){
    g_rowptr[i]=run; g_fill[i]=run;
    run += g_deg[i];
  }
  if(t==T-1) g_rowptr[NTOT] = sp[T-1];
}
__global__ void k_scatter(const int* __restrict__ adj, int E){
  int e = blockIdx.x*256 + threadIdx.x;
  if(e>=E) return;
  int src = __ldg(&adj[e]);
  int dst = __ldg(&adj[E+e]);
  int pos = atomicAdd(&g_fill[dst],1);
  if(pos<EMAX) g_col[pos]=src;
}

// ======================= Layer-1 node: z1 = fc1(Xf), s1/d1 =======================
__global__ void k_node1(const float* __restrict__ X,
                        const float* __restrict__ W,    // (32,64) row-major
                        const float* __restrict__ bvec,
                        const float* __restrict__ aW)   // (64)
{
  __shared__ float Ws[64*32];   // [j][k]
  __shared__ float aWs[64];
  __shared__ float bs[32];
  int tid = threadIdx.x;
  for(int i=tid;i<64*32;i+=256){ int k=i>>6, j=i&63; Ws[j*32+k]=W[i]; }
  if(tid<64) aWs[tid]=aW[tid];
  if(tid<32) bs[tid]=bvec[tid];
  __syncthreads();
  int lane=tid&31, wid=tid>>5;
  int n = blockIdx.x*8 + wid;
  if(n>=NTOT) return;
  int b=n/NLOC, loc=n-b*NLOC;
  // lane t<16 loads float4 = X[b, t, loc, 0:4]  (16B aligned)
  const float4* Xb = (const float4*)(X + ((size_t)b*TT*NLOC + loc)*NFEAT);
  float4 f4 = make_float4(0.f,0.f,0.f,0.f);
  if(lane<16) f4 = __ldg(&Xb[(size_t)lane*NLOC]);
  float a0=f4.x, a1=f4.y, a2=f4.z, a3=f4.w;
  float z = bs[lane];
  #pragma unroll
  for(int j=0;j<64;j++){
    float comp;
    switch(j&3){ case 0: comp=a0; break; case 1: comp=a1; break;
                 case 2: comp=a2; break; default: comp=a3; }
    float val = __shfl_sync(FULL, comp, j>>2);
    z = fmaf(Ws[j*32+lane], val, z);
  }
  float sv = warp_sum(z*aWs[lane]);
  float dv = warp_sum(z*aWs[32+lane]);
  g_z1[(size_t)n*H+lane] = z;
  if(lane==0){ g_s1[n]=sv; g_d1[n]=dv; }
}

// ============ Fused: gather layer-1 -> elu -> fc2 -> s2/d2 ============
__global__ void k_gat2(const float* __restrict__ W,    // (32,32)
                       const float* __restrict__ bvec,
                       const float* __restrict__ aW,   // (64)
                       const float* __restrict__ att_b1)
{
  __shared__ float Ws[32*32];
  __shared__ float aWs[64];
  __shared__ float bs[32];
  int tid=threadIdx.x;
  for(int i=tid;i<32*32;i+=256){ int k=i>>5, j=i&31; Ws[j*32+k]=W[i]; }
  if(tid<64) aWs[tid]=aW[tid];
  if(tid<32) bs[tid]=bvec[tid];
  __syncthreads();
  int lane=tid&31, wid=tid>>5;
  int n = blockIdx.x*8+wid;
  if(n>=NTOT) return;
  float dterm = g_d1[n] + __ldg(att_b1);
  int start = g_rowptr[n], end = g_rowptr[n+1];
  float acc = 0.f;
  for(int base=start; base<end; base+=32){
    int cnt = min(32, end-base);
    int   srcv = (lane<cnt) ? g_col[base+lane] : 0;
    float sv   = (lane<cnt) ? g_s1[srcv] : 0.f;
    int j=0;
    for(; j+1<cnt; j+=2){
      int s0=__shfl_sync(FULL,srcv,j), s1=__shfl_sync(FULL,srcv,j+1);
      float e0=lrelu(__shfl_sync(FULL,sv,j)+dterm);
      float e1=lrelu(__shfl_sync(FULL,sv,j+1)+dterm);
      float z0=g_z1[(size_t)s0*H+lane];
      float z1=g_z1[(size_t)s1*H+lane];
      acc = fmaf(z0,e0,acc);
      acc = fmaf(z1,e1,acc);
    }
    if(j<cnt){
      int s0=__shfl_sync(FULL,srcv,j);
      float e0=lrelu(__shfl_sync(FULL,sv,j)+dterm);
      acc = fmaf(g_z1[(size_t)s0*H+lane],e0,acc);
    }
  }
  float hin = eluf(acc);
  float z = bs[lane];
  #pragma unroll
  for(int j=0;j<32;j++) z = fmaf(Ws[j*32+lane], __shfl_sync(FULL,hin,j), z);
  float sv2 = warp_sum(z*aWs[lane]);
  float dv2 = warp_sum(z*aWs[32+lane]);
  g_z2[(size_t)n*H+lane]=z;
  if(lane==0){ g_s2[n]=sv2; g_d2[n]=dv2; }
}

// ==== Fused final: gather layer-2 -> elu -> GRU(h0=0) -> heads -> SIR -> out ====
__global__ void k_final(const float* __restrict__ X,
                        const float* __restrict__ states,
                        const float* __restrict__ Nvec,
                        const float* __restrict__ att_b2,
                        const float* __restrict__ Wih,  // (96,32)
                        const float* __restrict__ bih,
                        const float* __restrict__ bhh,
                        const float* __restrict__ WI, const float* __restrict__ bI,
                        const float* __restrict__ WR, const float* __restrict__ bR,
                        const float* __restrict__ Wsir, const float* __restrict__ bsir,
                        float* __restrict__ out)
{
  __shared__ float Wihs[32*96];  // [j][k]
  __shared__ float bihs[96], bhhs[96];
  __shared__ float Wh[18*34];    // 0-7 WI, 8-15 WR, 16-17 Wsir
  __shared__ float bh[18];
  __shared__ float stage[8][32];
  int tid=threadIdx.x;
  for(int i=tid;i<96*32;i+=256){ int k=i>>5, j=i&31; Wihs[j*96+k]=Wih[i]; }
  if(tid<96){ bihs[tid]=bih[tid]; bhhs[tid]=bhh[tid]; }
  for(int i=tid;i<8*34;i+=256){ Wh[i]=WI[i]; Wh[8*34+i]=WR[i]; }
  if(tid<2*34) Wh[16*34+tid]=Wsir[tid];
  if(tid<8) bh[tid]=bI[tid];
  else if(tid<16) bh[tid]=bR[tid-8];
  else if(tid<18) bh[tid]=bsir[tid-16];
  __syncthreads();
  int lane=tid&31, wid=tid>>5;
  int n = blockIdx.x*8+wid;
  if(n>=NTOT) return;

  // ---- gather layer 2 ----
  float dterm = g_d2[n] + __ldg(att_b2);
  int start = g_rowptr[n], end = g_rowptr[n+1];
  float acc = 0.f;
  for(int base=start; base<end; base+=32){
    int cnt = min(32, end-base);
    int   srcv = (lane<cnt) ? g_col[base+lane] : 0;
    float sv   = (lane<cnt) ? g_s2[srcv] : 0.f;
    int j=0;
    for(; j+1<cnt; j+=2){
      int s0=__shfl_sync(FULL,srcv,j), s1=__shfl_sync(FULL,srcv,j+1);
      float e0=lrelu(__shfl_sync(FULL,sv,j)+dterm);
      float e1=lrelu(__shfl_sync(FULL,sv,j+1)+dterm);
      float z0=g_z2[(size_t)s0*H+lane];
      float z1=g_z2[(size_t)s1*H+lane];
      acc = fmaf(z0,e0,acc);
      acc = fmaf(z1,e1,acc);
    }
    if(j<cnt){
      int s0=__shfl_sync(FULL,srcv,j);
      float e0=lrelu(__shfl_sync(FULL,sv,j)+dterm);
      acc = fmaf(g_z2[(size_t)s0*H+lane],e0,acc);
    }
  }
  float h2 = eluf(acc);

  // ---- GRU (h0 = 0) ----
  float gi0=bihs[lane], gi1=bihs[32+lane], gi2=bihs[64+lane];
  #pragma unroll
  for(int j=0;j<32;j++){
    float hv=__shfl_sync(FULL,h2,j);
    gi0=fmaf(Wihs[j*96+lane],    hv,gi0);
    gi1=fmaf(Wihs[j*96+32+lane], hv,gi1);
    gi2=fmaf(Wihs[j*96+64+lane], hv,gi2);
  }
  float r  = sigm(gi0 + bhhs[lane]);
  float zg = sigm(gi1 + bhhs[32+lane]);
  float nn = tanhf(gi2 + r*bhhs[64+lane]);
  float hout = (1.f-zg)*nn;

  int b=n/NLOC, loc=n-b*NLOC;
  const float* Xl = X + ((size_t)(b*TT+TT-1)*NLOC + loc)*NFEAT;
  float ldI = Xl[1], ldR = Xl[2];

  // 18 head rows across lanes; hc = [hout(32), ldI, ldR]
  float hacc = lane<18 ? bh[lane] : 0.f;
  #pragma unroll
  for(int j=0;j<32;j++){
    float hv=__shfl_sync(FULL,hout,j);
    if(lane<18) hacc = fmaf(Wh[lane*34+j],hv,hacc);
  }
  if(lane<18) hacc = fmaf(Wh[lane*34+32],ldI, fmaf(Wh[lane*34+33],ldR,hacc));
  float alpha = sigm(__shfl_sync(FULL, hacc, 16));
  float beta  = sigm(__shfl_sync(FULL, hacc, 17));

  if(lane<8)        stage[wid][2*lane]       = hacc;   // pred_I[h]
  else if(lane<16)  stage[wid][2*(lane-8)+1] = hacc;   // pred_R[h]

  // SIR rollout
  float I  = states[(size_t)n*2];
  float Rr = states[(size_t)n*2+1];
  float Nv = Nvec[loc];
  #pragma unroll
  for(int hh=0;hh<8;hh++){
    float S  = Nv - I - Rr;
    float dI = alpha*I*(S/Nv) - beta*I;
    float dR = beta*I;
    if(lane==16+2*hh) stage[wid][lane]=dI;
    if(lane==17+2*hh) stage[wid][lane]=dR;
    I += dI; Rr += dR;
  }
  __syncwarp();
  float v = stage[wid][lane];
  if(lane<16) out[(size_t)n*16+lane]=v;                               // pred
  else        out[(size_t)NTOT*16 + (size_t)n*16 + (lane-16)]=v;      // phy
}

extern "C" void kernel_launch(void* const* d_in, const int* in_sizes, int n_in,
                              void* d_out, int out_size)
{
  const float* X      = (const float*)d_in[0];
  const int*   adj    = (const int*)d_in[1];     // int32 in practice
  const float* states = (const float*)d_in[2];
  const float* Nvec   = (const float*)d_in[3];
  const float* fc1_W  = (const float*)d_in[4];
  const float* fc1_b  = (const float*)d_in[5];
  const float* att1_W = (const float*)d_in[6];
  const float* att1_b = (const float*)d_in[7];
  const float* fc2_W  = (const float*)d_in[8];
  const float* fc2_b  = (const float*)d_in[9];
  const float* att2_W = (const float*)d_in[10];
  const float* att2_b = (const float*)d_in[11];
  const float* gru_Wih= (const float*)d_in[12];
  /* d_in[13] = gru_Whh: unused (h0 == 0) */
  const float* gru_bih= (const float*)d_in[14];
  const float* gru_bhh= (const float*)d_in[15];
  const float* WI   = (const float*)d_in[16];
  const float* bI   = (const float*)d_in[17];
  const float* WR   = (const float*)d_in[18];
  const float* bR   = (const float*)d_in[19];
  const float* Wsir = (const float*)d_in[20];
  const float* bsir = (const float*)d_in[21];
  float* out = (float*)d_out;

  int E = in_sizes[1]/2;
  int nodeBlocks = (NTOT+7)/8;
  int eThreads = (E+255)/256;
  int nThreads = (NTOT+255)/256;

  // CSR build (graph is identical for both layers)
  k_zero   <<<nThreads,256>>>();
  k_hist   <<<eThreads,256>>>(adj, E);
  k_scan   <<<1,1024>>>();
  k_scatter<<<eThreads,256>>>(adj, E);
  // node pipeline
  k_node1<<<nodeBlocks,256>>>(X, fc1_W, fc1_b, att1_W);
  k_gat2 <<<nodeBlocks,256>>>(fc2_W, fc2_b, att2_W, att1_b);
  k_final<<<nodeBlocks,256>>>(X, states, Nvec, att2_b, gru_Wih, gru_bih, gru_bhh,
                              WI, bI, WR, bR, Wsir, bsir, out);
}

// round 10
// speedup vs baseline: 2.6400x; 2.6400x over previous
#include <cuda_runtime.h>
#include <math.h>

#define NLOC 50000
#define BB 4
#define TT 16
#define NFEAT 4
#define NTOT (BB*NLOC)   /* 200000 */
#define H 32
#define EMAX 1800000
#define FULL 0xffffffffu
#define SCAN_T 1024
#define SCAN_B ((NTOT+SCAN_T-1)/SCAN_T)   /* 196 */

// ---- device scratch ----
__device__ float g_z1[(size_t)NTOT*H];
__device__ float g_z2[(size_t)NTOT*H];
__device__ float g_s1[NTOT], g_d1[NTOT];
__device__ float g_s2[NTOT], g_d2[NTOT];
__device__ int   g_deg[NTOT];
__device__ int   g_scantmp[NTOT];
__device__ int   g_rowptr[NTOT+1];
__device__ int   g_fill[NTOT];
__device__ int   g_col[EMAX];
__device__ int   g_bsum[SCAN_B];
__device__ int   g_boff[SCAN_B];

__device__ __forceinline__ float warp_sum(float v){
  #pragma unroll
  for(int o=16;o;o>>=1) v += __shfl_xor_sync(FULL, v, o);
  return v;
}
__device__ __forceinline__ float sigm(float x){ return 1.f/(1.f+expf(-x)); }
__device__ __forceinline__ float eluf(float x){ return x>0.f ? x : expm1f(x); }
__device__ __forceinline__ float lrelu(float x){ return x>=0.f ? x : 0.01f*x; }

// ======================= CSR build =======================
__global__ void k_zero(){
  int n = blockIdx.x*256 + threadIdx.x;
  if(n<NTOT) g_deg[n]=0;
}
__global__ void k_hist(const int* __restrict__ adj, int E){
  int e = blockIdx.x*256 + threadIdx.x;
  if(e<E) atomicAdd(&g_deg[__ldg(&adj[E+e])], 1);
}
// phase A: per-block (1024-wide) inclusive scan, block totals
__global__ void k_scanA(){
  __shared__ int sp[SCAN_T];
  int t = threadIdx.x, b = blockIdx.x;
  int i = b*SCAN_T + t;
  int v = (i<NTOT) ? g_deg[i] : 0;
  sp[t]=v; __syncthreads();
  for(int off=1;off<SCAN_T;off<<=1){
    int u = (t>=off)? sp[t-off] : 0;
    __syncthreads();
    sp[t] += u;
    __syncthreads();
  }
  if(i<NTOT) g_scantmp[i]=sp[t];
  if(t==SCAN_T-1) g_bsum[b]=sp[t];
}
// phase B: scan the 196 block sums (single small block)
__global__ void k_scanB(){
  __shared__ int sp[256];
  int t = threadIdx.x;
  int v = (t<SCAN_B) ? g_bsum[t] : 0;
  sp[t]=v; __syncthreads();
  for(int off=1;off<256;off<<=1){
    int u = (t>=off)? sp[t-off] : 0;
    __syncthreads();
    sp[t] += u;
    __syncthreads();
  }
  if(t<SCAN_B) g_boff[t]=sp[t]-v;          // exclusive block offset
  if(t==SCAN_B-1) g_rowptr[NTOT]=sp[t];    // total edges
}
// phase C: write exclusive row pointers + fill cursors
__global__ void k_scanC(){
  int t = threadIdx.x, b = blockIdx.x;
  int i = b*SCAN_T + t;
  if(i<NTOT){
    int excl = g_scantmp[i] - g_deg[i] + g_boff[b];
    g_rowptr[i]=excl;
    g_fill[i]=excl;
  }
}
__global__ void k_scatter(const int* __restrict__ adj, int E){
  int e = blockIdx.x*256 + threadIdx.x;
  if(e>=E) return;
  int src = __ldg(&adj[e]);
  int dst = __ldg(&adj[E+e]);
  int pos = atomicAdd(&g_fill[dst],1);
  if(pos<EMAX) g_col[pos]=src;
}

// ============ Layer-1 node (THREAD-per-node): z1 = fc1(Xf), s1/d1 ============
__global__ void k_node1(const float* __restrict__ X,
                        const float* __restrict__ W,    // (32,64) row-major
                        const float* __restrict__ bvec,
                        const float* __restrict__ aW)   // (64)
{
  __shared__ float4 Wt4[64*8];  // Wt4[k*8+jj] = W[jj*4+c][k], c=0..3
  __shared__ float  aWs[64];
  __shared__ float4 bs4[8];
  int tid = threadIdx.x;
  for(int i=tid;i<512;i+=256){
    int k=i>>3, jj=i&7;
    Wt4[i] = make_float4(W[(jj*4+0)*64+k], W[(jj*4+1)*64+k],
                         W[(jj*4+2)*64+k], W[(jj*4+3)*64+k]);
  }
  if(tid<64) aWs[tid]=aW[tid];
  if(tid<8)  bs4[tid]=make_float4(bvec[tid*4],bvec[tid*4+1],bvec[tid*4+2],bvec[tid*4+3]);
  __syncthreads();
  int stride = gridDim.x*256;
  for(int n = blockIdx.x*256 + tid; n<NTOT; n+=stride){
    int b = n/NLOC, loc = n-b*NLOC;
    float4 acc[8];
    #pragma unroll
    for(int jj=0;jj<8;jj++) acc[jj]=bs4[jj];
    const float4* Xp = ((const float4*)X) + (size_t)b*TT*NLOC + loc;
    #pragma unroll
    for(int t=0;t<TT;t++){
      float4 xv = __ldg(Xp + (size_t)t*NLOC);
      #pragma unroll
      for(int c=0;c<4;c++){
        float x = (c==0)?xv.x:(c==1)?xv.y:(c==2)?xv.z:xv.w;
        const float4* wr = &Wt4[(t*4+c)*8];
        #pragma unroll
        for(int jj=0;jj<8;jj++){
          float4 w = wr[jj];
          acc[jj].x = fmaf(w.x,x,acc[jj].x);
          acc[jj].y = fmaf(w.y,x,acc[jj].y);
          acc[jj].z = fmaf(w.z,x,acc[jj].z);
          acc[jj].w = fmaf(w.w,x,acc[jj].w);
        }
      }
    }
    float s=0.f, d=0.f;
    #pragma unroll
    for(int jj=0;jj<8;jj++){
      s = fmaf(acc[jj].x,aWs[jj*4+0], fmaf(acc[jj].y,aWs[jj*4+1],
          fmaf(acc[jj].z,aWs[jj*4+2], fmaf(acc[jj].w,aWs[jj*4+3], s))));
      d = fmaf(acc[jj].x,aWs[32+jj*4+0], fmaf(acc[jj].y,aWs[32+jj*4+1],
          fmaf(acc[jj].z,aWs[32+jj*4+2], fmaf(acc[jj].w,aWs[32+jj*4+3], d))));
    }
    float4* zp = ((float4*)g_z1) + (size_t)n*8;
    #pragma unroll
    for(int jj=0;jj<8;jj++) zp[jj]=acc[jj];
    g_s1[n]=s; g_d1[n]=d;
  }
}

// ======== Fused (WARP-per-node, grid-stride, W in regs): gather1->elu->fc2->s2/d2 ========
__global__ void k_gat2(const float* __restrict__ W,    // (32,32)
                       const float* __restrict__ bvec,
                       const float* __restrict__ aW,   // (64)
                       const float* __restrict__ att_b1)
{
  int tid=threadIdx.x;
  int lane=tid&31, wid=tid>>5;
  // per-lane weight row (output = lane): W[lane][0..31]
  float Wreg[32];
  {
    const float4* Wr = (const float4*)(W + lane*32);
    #pragma unroll
    for(int q=0;q<8;q++){
      float4 w = __ldg(&Wr[q]);
      Wreg[q*4+0]=w.x; Wreg[q*4+1]=w.y; Wreg[q*4+2]=w.z; Wreg[q*4+3]=w.w;
    }
  }
  float breg = __ldg(&bvec[lane]);
  float aw_s = __ldg(&aW[lane]);
  float aw_d = __ldg(&aW[32+lane]);
  float ab1  = __ldg(att_b1);
  int nWarps = gridDim.x*8;
  for(int n = blockIdx.x*8 + wid; n<NTOT; n+=nWarps){
    float dterm = g_d1[n] + ab1;
    int start = g_rowptr[n], end = g_rowptr[n+1];
    float acc = 0.f;
    for(int base=start; base<end; base+=32){
      int cnt = min(32, end-base);
      int   srcv = (lane<cnt) ? g_col[base+lane] : 0;
      float sv   = (lane<cnt) ? g_s1[srcv] : 0.f;
      int j=0;
      for(; j+1<cnt; j+=2){
        int s0=__shfl_sync(FULL,srcv,j), s1=__shfl_sync(FULL,srcv,j+1);
        float e0=lrelu(__shfl_sync(FULL,sv,j)+dterm);
        float e1=lrelu(__shfl_sync(FULL,sv,j+1)+dterm);
        float z0=g_z1[(size_t)s0*H+lane];
        float z1=g_z1[(size_t)s1*H+lane];
        acc = fmaf(z0,e0,acc);
        acc = fmaf(z1,e1,acc);
      }
      if(j<cnt){
        int s0=__shfl_sync(FULL,srcv,j);
        float e0=lrelu(__shfl_sync(FULL,sv,j)+dterm);
        acc = fmaf(g_z1[(size_t)s0*H+lane],e0,acc);
      }
    }
    float hin = eluf(acc);
    float z = breg;
    #pragma unroll
    for(int k=0;k<32;k++) z = fmaf(Wreg[k], __shfl_sync(FULL,hin,k), z);
    float sv2 = warp_sum(z*aw_s);
    float dv2 = warp_sum(z*aw_d);
    g_z2[(size_t)n*H+lane]=z;
    if(lane==0){ g_s2[n]=sv2; g_d2[n]=dv2; }
  }
}

// ==== Fused final (WARP-per-node, grid-stride): gather2->elu->GRU->heads->SIR->out ====
__global__ void k_final(const float* __restrict__ X,
                        const float* __restrict__ states,
                        const float* __restrict__ Nvec,
                        const float* __restrict__ att_b2,
                        const float* __restrict__ Wih,  // (96,32)
                        const float* __restrict__ bih,
                        const float* __restrict__ bhh,
                        const float* __restrict__ WI, const float* __restrict__ bI,
                        const float* __restrict__ WR, const float* __restrict__ bR,
                        const float* __restrict__ Wsir, const float* __restrict__ bsir,
                        float* __restrict__ out)
{
  __shared__ float4 W4[32*32];   // W4[k*32+j] = (Wih_r[j][k], Wih_z[j][k], Wih_n[j][k], 0)
  __shared__ float Wh[18*34];    // 0-7 WI, 8-15 WR, 16-17 Wsir
  __shared__ float bh[18];
  __shared__ float stage[8][32];
  int tid=threadIdx.x;
  for(int i=tid;i<1024;i+=256){
    int k=i>>5, j=i&31;
    W4[i] = make_float4(Wih[j*32+k], Wih[(j+32)*32+k], Wih[(j+64)*32+k], 0.f);
  }
  for(int i=tid;i<8*34;i+=256){ Wh[i]=WI[i]; Wh[8*34+i]=WR[i]; }
  if(tid<2*34) Wh[16*34+tid]=Wsir[tid];
  if(tid<8) bh[tid]=bI[tid];
  else if(tid<16) bh[tid]=bR[tid-8];
  else if(tid<18) bh[tid]=bsir[tid-16];
  __syncthreads();
  int lane=tid&31, wid=tid>>5;
  float bih0=__ldg(&bih[lane]), bih1=__ldg(&bih[32+lane]), bih2=__ldg(&bih[64+lane]);
  float bhh0=__ldg(&bhh[lane]), bhh1=__ldg(&bhh[32+lane]), bhh2=__ldg(&bhh[64+lane]);
  float ab2 = __ldg(att_b2);
  int nWarps = gridDim.x*8;
  for(int n = blockIdx.x*8 + wid; n<NTOT; n+=nWarps){
    // ---- gather layer 2 ----
    float dterm = g_d2[n] + ab2;
    int start = g_rowptr[n], end = g_rowptr[n+1];
    float acc = 0.f;
    for(int base=start; base<end; base+=32){
      int cnt = min(32, end-base);
      int   srcv = (lane<cnt) ? g_col[base+lane] : 0;
      float sv   = (lane<cnt) ? g_s2[srcv] : 0.f;
      int j=0;
      for(; j+1<cnt; j+=2){
        int s0=__shfl_sync(FULL,srcv,j), s1=__shfl_sync(FULL,srcv,j+1);
        float e0=lrelu(__shfl_sync(FULL,sv,j)+dterm);
        float e1=lrelu(__shfl_sync(FULL,sv,j+1)+dterm);
        float z0=g_z2[(size_t)s0*H+lane];
        float z1=g_z2[(size_t)s1*H+lane];
        acc = fmaf(z0,e0,acc);
        acc = fmaf(z1,e1,acc);
      }
      if(j<cnt){
        int s0=__shfl_sync(FULL,srcv,j);
        float e0=lrelu(__shfl_sync(FULL,sv,j)+dterm);
        acc = fmaf(g_z2[(size_t)s0*H+lane],e0,acc);
      }
    }
    float h2 = eluf(acc);

    // ---- GRU (h0 = 0): 32 LDS.128 + 32 SHFL + 96 FMA ----
    float gi0=bih0, gi1=bih1, gi2=bih2;
    #pragma unroll
    for(int k=0;k<32;k++){
      float hv=__shfl_sync(FULL,h2,k);
      float4 w = W4[k*32+lane];
      gi0=fmaf(w.x,hv,gi0);
      gi1=fmaf(w.y,hv,gi1);
      gi2=fmaf(w.z,hv,gi2);
    }
    float r  = sigm(gi0 + bhh0);
    float zg = sigm(gi1 + bhh1);
    float nn = tanhf(gi2 + r*bhh2);
    float hout = (1.f-zg)*nn;

    int b=n/NLOC, loc=n-b*NLOC;
    const float* Xl = X + ((size_t)(b*TT+TT-1)*NLOC + loc)*NFEAT;
    float ldI = __ldg(&Xl[1]), ldR = __ldg(&Xl[2]);

    // 18 head rows across lanes; hc = [hout(32), ldI, ldR]
    float hacc = lane<18 ? bh[lane] : 0.f;
    #pragma unroll
    for(int j=0;j<32;j++){
      float hv=__shfl_sync(FULL,hout,j);
      if(lane<18) hacc = fmaf(Wh[lane*34+j],hv,hacc);
    }
    if(lane<18) hacc = fmaf(Wh[lane*34+32],ldI, fmaf(Wh[lane*34+33],ldR,hacc));
    float alpha = sigm(__shfl_sync(FULL, hacc, 16));
    float beta  = sigm(__shfl_sync(FULL, hacc, 17));

    if(lane<8)        stage[wid][2*lane]       = hacc;   // pred_I[h]
    else if(lane<16)  stage[wid][2*(lane-8)+1] = hacc;   // pred_R[h]

    float I  = __ldg(&states[(size_t)n*2]);
    float Rr = __ldg(&states[(size_t)n*2+1]);
    float Nv = __ldg(&Nvec[loc]);
    #pragma unroll
    for(int hh=0;hh<8;hh++){
      float S  = Nv - I - Rr;
      float dI = alpha*I*(S/Nv) - beta*I;
      float dR = beta*I;
      if(lane==16+2*hh) stage[wid][lane]=dI;
      if(lane==17+2*hh) stage[wid][lane]=dR;
      I += dI; Rr += dR;
    }
    __syncwarp();
    float v = stage[wid][lane];
    if(lane<16) out[(size_t)n*16+lane]=v;
    else        out[(size_t)NTOT*16 + (size_t)n*16 + (lane-16)]=v;
    __syncwarp();
  }
}

extern "C" void kernel_launch(void* const* d_in, const int* in_sizes, int n_in,
                              void* d_out, int out_size)
{
  const float* X      = (const float*)d_in[0];
  const int*   adj    = (const int*)d_in[1];     // int32 in practice
  const float* states = (const float*)d_in[2];
  const float* Nvec   = (const float*)d_in[3];
  const float* fc1_W  = (const float*)d_in[4];
  const float* fc1_b  = (const float*)d_in[5];
  const float* att1_W = (const float*)d_in[6];
  const float* att1_b = (const float*)d_in[7];
  const float* fc2_W  = (const float*)d_in[8];
  const float* fc2_b  = (const float*)d_in[9];
  const float* att2_W = (const float*)d_in[10];
  const float* att2_b = (const float*)d_in[11];
  const float* gru_Wih= (const float*)d_in[12];
  /* d_in[13] = gru_Whh: unused (h0 == 0) */
  const float* gru_bih= (const float*)d_in[14];
  const float* gru_bhh= (const float*)d_in[15];
  const float* WI   = (const float*)d_in[16];
  const float* bI   = (const float*)d_in[17];
  const float* WR   = (const float*)d_in[18];
  const float* bR   = (const float*)d_in[19];
  const float* Wsir = (const float*)d_in[20];
  const float* bsir = (const float*)d_in[21];
  float* out = (float*)d_out;

  int E = in_sizes[1]/2;
  int eB = (E+255)/256;
  int nB = (NTOT+255)/256;

  // CSR build
  k_zero   <<<nB,256>>>();
  k_hist   <<<eB,256>>>(adj, E);
  k_scanA  <<<SCAN_B,SCAN_T>>>();
  k_scanB  <<<1,256>>>();
  k_scanC  <<<SCAN_B,SCAN_T>>>();
  k_scatter<<<eB,256>>>(adj, E);
  // node pipeline
  k_node1<<<782,256>>>(X, fc1_W, fc1_b, att1_W);
  k_gat2 <<<1480,256>>>(fc2_W, fc2_b, att2_W, att1_b);
  k_final<<<1480,256>>>(X, states, Nvec, att2_b, gru_Wih, gru_bih, gru_bhh,
                        WI, bI, WR, bR, Wsir, bsir, out);
}

// round 11
// speedup vs baseline: 2.9380x; 1.1129x over previous
#include <cuda_runtime.h>
#include <math.h>

#define NLOC 50000
#define BB 4
#define TT 16
#define NFEAT 4
#define NTOT (BB*NLOC)   /* 200000 */
#define H 32
#define EMAX 1800000
#define FULL 0xffffffffu
#define SCAN_T 1024
#define SCAN_B ((NTOT+SCAN_T-1)/SCAN_T)   /* 196 */

// ---- device scratch ----
__device__ float g_z1[(size_t)NTOT*H];
__device__ float g_z2[(size_t)NTOT*H];
__device__ float g_s1[NTOT], g_d1[NTOT];
__device__ float g_s2[NTOT], g_d2[NTOT];
__device__ int   g_deg[NTOT];
__device__ int   g_scantmp[NTOT];
__device__ int   g_rowptr[NTOT+1];
__device__ int   g_fill[NTOT];
__device__ int   g_col[EMAX];
__device__ int   g_bsum[SCAN_B];
__device__ int   g_boff[SCAN_B];

__device__ __forceinline__ float warp_sum(float v){
  #pragma unroll
  for(int o=16;o;o>>=1) v += __shfl_xor_sync(FULL, v, o);
  return v;
}
__device__ __forceinline__ float sigm(float x){ return 1.f/(1.f+expf(-x)); }
__device__ __forceinline__ float eluf(float x){ return x>0.f ? x : expm1f(x); }
__device__ __forceinline__ float lrelu(float x){ return x>=0.f ? x : 0.01f*x; }

// ---- high-MLP gather: warp = 4 edges x 8 float4-lanes, 2 rounds in flight ----
// returns: this lane's feature (= lane index) of sum_e z[src_e]*lrelu(s[src_e]+dterm)
__device__ __forceinline__ float gather_row(const float* __restrict__ zarr,
                                            const float* __restrict__ sarr,
                                            int start, int end, float dterm, int lane)
{
  int eoff = lane>>3;    // edge slot 0..3
  int fv   = lane&7;     // float4 slot in the 32-float row
  float4 a0 = make_float4(0.f,0.f,0.f,0.f);
  float4 a1 = make_float4(0.f,0.f,0.f,0.f);
  for(int base=start; base<end; base+=8){
    int i0 = base+eoff, i1 = base+4+eoff;
    bool v0 = i0<end, v1 = i1<end;
    int s0 = v0 ? __ldg(&g_col[i0]) : 0;
    int s1 = v1 ? __ldg(&g_col[i1]) : 0;
    float sv0 = __ldg(&sarr[s0]);
    float sv1 = __ldg(&sarr[s1]);
    float e0 = v0 ? lrelu(sv0+dterm) : 0.f;
    float e1 = v1 ? lrelu(sv1+dterm) : 0.f;
    float4 z0 = __ldg(((const float4*)(zarr + (size_t)s0*H)) + fv);
    float4 z1 = __ldg(((const float4*)(zarr + (size_t)s1*H)) + fv);
    a0.x=fmaf(z0.x,e0,a0.x); a0.y=fmaf(z0.y,e0,a0.y);
    a0.z=fmaf(z0.z,e0,a0.z); a0.w=fmaf(z0.w,e0,a0.w);
    a1.x=fmaf(z1.x,e1,a1.x); a1.y=fmaf(z1.y,e1,a1.y);
    a1.z=fmaf(z1.z,e1,a1.z); a1.w=fmaf(z1.w,e1,a1.w);
  }
  a0.x+=a1.x; a0.y+=a1.y; a0.z+=a1.z; a0.w+=a1.w;
  // reduce across the 4 edge slots (lane bits 3,4)
  #pragma unroll
  for(int off=8; off<=16; off<<=1){
    a0.x += __shfl_xor_sync(FULL,a0.x,off);
    a0.y += __shfl_xor_sync(FULL,a0.y,off);
    a0.z += __shfl_xor_sync(FULL,a0.z,off);
    a0.w += __shfl_xor_sync(FULL,a0.w,off);
  }
  // redistribute: lane k wants feature k -> float4 slot k>>2 (held by lane k>>2), comp k&3
  int sl = lane>>2;
  float cx = __shfl_sync(FULL,a0.x,sl);
  float cy = __shfl_sync(FULL,a0.y,sl);
  float cz = __shfl_sync(FULL,a0.z,sl);
  float cw = __shfl_sync(FULL,a0.w,sl);
  int c = lane&3;
  return (c==0)?cx:(c==1)?cy:(c==2)?cz:cw;
}

// ======================= CSR build =======================
__global__ void k_zero(){
  int n = blockIdx.x*256 + threadIdx.x;
  if(n<NTOT) g_deg[n]=0;
}
__global__ void k_hist(const int* __restrict__ adj, int E){
  int e = blockIdx.x*256 + threadIdx.x;
  if(e<E) atomicAdd(&g_deg[__ldg(&adj[E+e])], 1);
}
__global__ void k_scanA(){
  __shared__ int sp[SCAN_T];
  int t = threadIdx.x, b = blockIdx.x;
  int i = b*SCAN_T + t;
  int v = (i<NTOT) ? g_deg[i] : 0;
  sp[t]=v; __syncthreads();
  for(int off=1;off<SCAN_T;off<<=1){
    int u = (t>=off)? sp[t-off] : 0;
    __syncthreads();
    sp[t] += u;
    __syncthreads();
  }
  if(i<NTOT) g_scantmp[i]=sp[t];
  if(t==SCAN_T-1) g_bsum[b]=sp[t];
}
__global__ void k_scanB(){
  __shared__ int sp[256];
  int t = threadIdx.x;
  int v = (t<SCAN_B) ? g_bsum[t] : 0;
  sp[t]=v; __syncthreads();
  for(int off=1;off<256;off<<=1){
    int u = (t>=off)? sp[t-off] : 0;
    __syncthreads();
    sp[t] += u;
    __syncthreads();
  }
  if(t<SCAN_B) g_boff[t]=sp[t]-v;
  if(t==SCAN_B-1) g_rowptr[NTOT]=sp[t];
}
__global__ void k_scanC(){
  int t = threadIdx.x, b = blockIdx.x;
  int i = b*SCAN_T + t;
  if(i<NTOT){
    int excl = g_scantmp[i] - g_deg[i] + g_boff[b];
    g_rowptr[i]=excl;
    g_fill[i]=excl;
  }
}
__global__ void k_scatter(const int* __restrict__ adj, int E){
  int e = blockIdx.x*256 + threadIdx.x;
  if(e>=E) return;
  int src = __ldg(&adj[e]);
  int dst = __ldg(&adj[E+e]);
  int pos = atomicAdd(&g_fill[dst],1);
  if(pos<EMAX) g_col[pos]=src;
}

// ============ Layer-1 node (THREAD-per-node): z1 = fc1(Xf), s1/d1 ============
__global__ void k_node1(const float* __restrict__ X,
                        const float* __restrict__ W,    // (32,64) row-major
                        const float* __restrict__ bvec,
                        const float* __restrict__ aW)   // (64)
{
  __shared__ float4 Wt4[64*8];  // Wt4[k*8+jj] = W[jj*4+c][k]
  __shared__ float  aWs[64];
  __shared__ float4 bs4[8];
  int tid = threadIdx.x;
  for(int i=tid;i<512;i+=256){
    int k=i>>3, jj=i&7;
    Wt4[i] = make_float4(W[(jj*4+0)*64+k], W[(jj*4+1)*64+k],
                         W[(jj*4+2)*64+k], W[(jj*4+3)*64+k]);
  }
  if(tid<64) aWs[tid]=aW[tid];
  if(tid<8)  bs4[tid]=make_float4(bvec[tid*4],bvec[tid*4+1],bvec[tid*4+2],bvec[tid*4+3]);
  __syncthreads();
  int stride = gridDim.x*256;
  for(int n = blockIdx.x*256 + tid; n<NTOT; n+=stride){
    int b = n/NLOC, loc = n-b*NLOC;
    float4 acc[8];
    #pragma unroll
    for(int jj=0;jj<8;jj++) acc[jj]=bs4[jj];
    const float4* Xp = ((const float4*)X) + (size_t)b*TT*NLOC + loc;
    #pragma unroll
    for(int t=0;t<TT;t++){
      float4 xv = __ldg(Xp + (size_t)t*NLOC);
      #pragma unroll
      for(int c=0;c<4;c++){
        float x = (c==0)?xv.x:(c==1)?xv.y:(c==2)?xv.z:xv.w;
        const float4* wr = &Wt4[(t*4+c)*8];
        #pragma unroll
        for(int jj=0;jj<8;jj++){
          float4 w = wr[jj];
          acc[jj].x = fmaf(w.x,x,acc[jj].x);
          acc[jj].y = fmaf(w.y,x,acc[jj].y);
          acc[jj].z = fmaf(w.z,x,acc[jj].z);
          acc[jj].w = fmaf(w.w,x,acc[jj].w);
        }
      }
    }
    float s=0.f, d=0.f;
    #pragma unroll
    for(int jj=0;jj<8;jj++){
      s = fmaf(acc[jj].x,aWs[jj*4+0], fmaf(acc[jj].y,aWs[jj*4+1],
          fmaf(acc[jj].z,aWs[jj*4+2], fmaf(acc[jj].w,aWs[jj*4+3], s))));
      d = fmaf(acc[jj].x,aWs[32+jj*4+0], fmaf(acc[jj].y,aWs[32+jj*4+1],
          fmaf(acc[jj].z,aWs[32+jj*4+2], fmaf(acc[jj].w,aWs[32+jj*4+3], d))));
    }
    float4* zp = ((float4*)g_z1) + (size_t)n*8;
    #pragma unroll
    for(int jj=0;jj<8;jj++) zp[jj]=acc[jj];
    g_s1[n]=s; g_d1[n]=d;
  }
}

// ======== Fused (WARP-per-node, grid-stride): gather1 -> elu -> fc2 -> s2/d2 ========
__global__ void k_gat2(const float* __restrict__ W,    // (32,32)
                       const float* __restrict__ bvec,
                       const float* __restrict__ aW,   // (64)
                       const float* __restrict__ att_b1)
{
  int tid=threadIdx.x;
  int lane=tid&31, wid=tid>>5;
  float Wreg[32];
  {
    const float4* Wr = (const float4*)(W + lane*32);
    #pragma unroll
    for(int q=0;q<8;q++){
      float4 w = __ldg(&Wr[q]);
      Wreg[q*4+0]=w.x; Wreg[q*4+1]=w.y; Wreg[q*4+2]=w.z; Wreg[q*4+3]=w.w;
    }
  }
  float breg = __ldg(&bvec[lane]);
  float aw_s = __ldg(&aW[lane]);
  float aw_d = __ldg(&aW[32+lane]);
  float ab1  = __ldg(att_b1);
  int nWarps = gridDim.x*8;
  for(int n = blockIdx.x*8 + wid; n<NTOT; n+=nWarps){
    float dterm = g_d1[n] + ab1;
    int start = g_rowptr[n], end = g_rowptr[n+1];
    float acc = gather_row(g_z1, g_s1, start, end, dterm, lane);
    float hin = eluf(acc);
    float z = breg;
    #pragma unroll
    for(int k=0;k<32;k++) z = fmaf(Wreg[k], __shfl_sync(FULL,hin,k), z);
    float sv2 = warp_sum(z*aw_s);
    float dv2 = warp_sum(z*aw_d);
    g_z2[(size_t)n*H+lane]=z;
    if(lane==0){ g_s2[n]=sv2; g_d2[n]=dv2; }
  }
}

// ==== Fused final (WARP-per-node): gather2 -> elu -> GRU -> heads -> SIR -> out ====
__global__ void k_final(const float* __restrict__ X,
                        const float* __restrict__ states,
                        const float* __restrict__ Nvec,
                        const float* __restrict__ att_b2,
                        const float* __restrict__ Wih,  // (96,32)
                        const float* __restrict__ bih,
                        const float* __restrict__ bhh,
                        const float* __restrict__ WI, const float* __restrict__ bI,
                        const float* __restrict__ WR, const float* __restrict__ bR,
                        const float* __restrict__ Wsir, const float* __restrict__ bsir,
                        float* __restrict__ out)
{
  __shared__ float4 W4[32*32];   // W4[k*32+j] = (Wih_r[j][k], Wih_z[j][k], Wih_n[j][k], 0)
  __shared__ float Wh[18*34];
  __shared__ float bh[18];
  __shared__ float stage[8][32];
  int tid=threadIdx.x;
  for(int i=tid;i<1024;i+=256){
    int k=i>>5, j=i&31;
    W4[i] = make_float4(Wih[j*32+k], Wih[(j+32)*32+k], Wih[(j+64)*32+k], 0.f);
  }
  for(int i=tid;i<8*34;i+=256){ Wh[i]=WI[i]; Wh[8*34+i]=WR[i]; }
  if(tid<2*34) Wh[16*34+tid]=Wsir[tid];
  if(tid<8) bh[tid]=bI[tid];
  else if(tid<16) bh[tid]=bR[tid-8];
  else if(tid<18) bh[tid]=bsir[tid-16];
  __syncthreads();
  int lane=tid&31, wid=tid>>5;
  float bih0=__ldg(&bih[lane]), bih1=__ldg(&bih[32+lane]), bih2=__ldg(&bih[64+lane]);
  float bhh0=__ldg(&bhh[lane]), bhh1=__ldg(&bhh[32+lane]), bhh2=__ldg(&bhh[64+lane]);
  float ab2 = __ldg(att_b2);
  int nWarps = gridDim.x*8;
  for(int n = blockIdx.x*8 + wid; n<NTOT; n+=nWarps){
    float dterm = g_d2[n] + ab2;
    int start = g_rowptr[n], end = g_rowptr[n+1];
    float acc = gather_row(g_z2, g_s2, start, end, dterm, lane);
    float h2 = eluf(acc);

    float gi0=bih0, gi1=bih1, gi2=bih2;
    #pragma unroll
    for(int k=0;k<32;k++){
      float hv=__shfl_sync(FULL,h2,k);
      float4 w = W4[k*32+lane];
      gi0=fmaf(w.x,hv,gi0);
      gi1=fmaf(w.y,hv,gi1);
      gi2=fmaf(w.z,hv,gi2);
    }
    float r  = sigm(gi0 + bhh0);
    float zg = sigm(gi1 + bhh1);
    float nn = tanhf(gi2 + r*bhh2);
    float hout = (1.f-zg)*nn;

    int b=n/NLOC, loc=n-b*NLOC;
    const float* Xl = X + ((size_t)(b*TT+TT-1)*NLOC + loc)*NFEAT;
    float ldI = __ldg(&Xl[1]), ldR = __ldg(&Xl[2]);

    float hacc = lane<18 ? bh[lane] : 0.f;
    #pragma unroll
    for(int j=0;j<32;j++){
      float hv=__shfl_sync(FULL,hout,j);
      if(lane<18) hacc = fmaf(Wh[lane*34+j],hv,hacc);
    }
    if(lane<18) hacc = fmaf(Wh[lane*34+32],ldI, fmaf(Wh[lane*34+33],ldR,hacc));
    float alpha = sigm(__shfl_sync(FULL, hacc, 16));
    float beta  = sigm(__shfl_sync(FULL, hacc, 17));

    if(lane<8)        stage[wid][2*lane]       = hacc;   // pred_I[h]
    else if(lane<16)  stage[wid][2*(lane-8)+1] = hacc;   // pred_R[h]

    float I  = __ldg(&states[(size_t)n*2]);
    float Rr = __ldg(&states[(size_t)n*2+1]);
    float Nv = __ldg(&Nvec[loc]);
    #pragma unroll
    for(int hh=0;hh<8;hh++){
      float S  = Nv - I - Rr;
      float dI = alpha*I*(S/Nv) - beta*I;
      float dR = beta*I;
      if(lane==16+2*hh) stage[wid][lane]=dI;
      if(lane==17+2*hh) stage[wid][lane]=dR;
      I += dI; Rr += dR;
    }
    __syncwarp();
    float v = stage[wid][lane];
    if(lane<16) out[(size_t)n*16+lane]=v;
    else        out[(size_t)NTOT*16 + (size_t)n*16 + (lane-16)]=v;
    __syncwarp();
  }
}

extern "C" void kernel_launch(void* const* d_in, const int* in_sizes, int n_in,
                              void* d_out, int out_size)
{
  const float* X      = (const float*)d_in[0];
  const int*   adj    = (const int*)d_in[1];     // int32 in practice
  const float* states = (const float*)d_in[2];
  const float* Nvec   = (const float*)d_in[3];
  const float* fc1_W  = (const float*)d_in[4];
  const float* fc1_b  = (const float*)d_in[5];
  const float* att1_W = (const float*)d_in[6];
  const float* att1_b = (const float*)d_in[7];
  const float* fc2_W  = (const float*)d_in[8];
  const float* fc2_b  = (const float*)d_in[9];
  const float* att2_W = (const float*)d_in[10];
  const float* att2_b = (const float*)d_in[11];
  const float* gru_Wih= (const float*)d_in[12];
  /* d_in[13] = gru_Whh: unused (h0 == 0) */
  const float* gru_bih= (const float*)d_in[14];
  const float* gru_bhh= (const float*)d_in[15];
  const float* WI   = (const float*)d_in[16];
  const float* bI   = (const float*)d_in[17];
  const float* WR   = (const float*)d_in[18];
  const float* bR   = (const float*)d_in[19];
  const float* Wsir = (const float*)d_in[20];
  const float* bsir = (const float*)d_in[21];
  float* out = (float*)d_out;

  int E = in_sizes[1]/2;
  int eB = (E+255)/256;
  int nB = (NTOT+255)/256;

  // order chosen so k_node1 sits at kernel index 3 (ncu samples index 3)
  k_zero   <<<nB,256>>>();
  k_hist   <<<eB,256>>>(adj, E);
  k_scanA  <<<SCAN_B,SCAN_T>>>();
  k_node1  <<<782,256>>>(X, fc1_W, fc1_b, att1_W);   // no CSR dependency
  k_scanB  <<<1,256>>>();
  k_scanC  <<<SCAN_B,SCAN_T>>>();
  k_scatter<<<eB,256>>>(adj, E);
  k_gat2   <<<1480,256>>>(fc2_W, fc2_b, att2_W, att1_b);
  k_final  <<<1480,256>>>(X, states, Nvec, att2_b, gru_Wih, gru_bih, gru_bhh,
                          WI, bI, WR, bR, Wsir, bsir, out);
}

// round 12
// speedup vs baseline: 2.9510x; 1.0044x over previous
#include <cuda_runtime.h>
#include <math.h>

#define NLOC 50000
#define BB 4
#define TT 16
#define NFEAT 4
#define NTOT (BB*NLOC)   /* 200000 */
#define H 32
#define EMAX 1800000
#define FULL 0xffffffffu
#define SCAN_T 1024
#define SCAN_B ((NTOT+SCAN_T-1)/SCAN_T)   /* 196 */

// ---- device scratch ----
__device__ float g_z1[(size_t)NTOT*H];
__device__ float g_z2[(size_t)NTOT*H];
__device__ float g_s1[NTOT], g_d1[NTOT];
__device__ float g_s2[NTOT], g_d2[NTOT];
__device__ int   g_deg[NTOT];
__device__ int   g_scantmp[NTOT];
__device__ int   g_rowptr[NTOT+1];
__device__ int   g_fill[NTOT];
__device__ int   g_col[EMAX];
__device__ int   g_bsum[SCAN_B];

__device__ __forceinline__ float sigm(float x){ return 1.f/(1.f+expf(-x)); }
__device__ __forceinline__ float eluf(float x){ return x>0.f ? x : expm1f(x); }
__device__ __forceinline__ float lrelu(float x){ return x>=0.f ? x : 0.01f*x; }

// ---- high-MLP gather: warp = 4 edges x 8 float4-lanes, 2 rounds in flight ----
// returns this lane's feature (= lane index) of sum_e z[src_e]*lrelu(s[src_e]+dterm)
__device__ __forceinline__ float gather_row(const float* __restrict__ zarr,
                                            const float* __restrict__ sarr,
                                            int start, int end, float dterm, int lane)
{
  int eoff = lane>>3;    // edge slot 0..3
  int fv   = lane&7;     // float4 slot in the 32-float row
  float4 a0 = make_float4(0.f,0.f,0.f,0.f);
  float4 a1 = make_float4(0.f,0.f,0.f,0.f);
  for(int base=start; base<end; base+=8){
    int i0 = base+eoff, i1 = base+4+eoff;
    bool v0 = i0<end, v1 = i1<end;
    int s0 = v0 ? __ldg(&g_col[i0]) : 0;
    int s1 = v1 ? __ldg(&g_col[i1]) : 0;
    float sv0 = __ldg(&sarr[s0]);
    float sv1 = __ldg(&sarr[s1]);
    float e0 = v0 ? lrelu(sv0+dterm) : 0.f;
    float e1 = v1 ? lrelu(sv1+dterm) : 0.f;
    float4 z0 = __ldg(((const float4*)(zarr + (size_t)s0*H)) + fv);
    float4 z1 = __ldg(((const float4*)(zarr + (size_t)s1*H)) + fv);
    a0.x=fmaf(z0.x,e0,a0.x); a0.y=fmaf(z0.y,e0,a0.y);
    a0.z=fmaf(z0.z,e0,a0.z); a0.w=fmaf(z0.w,e0,a0.w);
    a1.x=fmaf(z1.x,e1,a1.x); a1.y=fmaf(z1.y,e1,a1.y);
    a1.z=fmaf(z1.z,e1,a1.z); a1.w=fmaf(z1.w,e1,a1.w);
  }
  a0.x+=a1.x; a0.y+=a1.y; a0.z+=a1.z; a0.w+=a1.w;
  #pragma unroll
  for(int off=8; off<=16; off<<=1){
    a0.x += __shfl_xor_sync(FULL,a0.x,off);
    a0.y += __shfl_xor_sync(FULL,a0.y,off);
    a0.z += __shfl_xor_sync(FULL,a0.z,off);
    a0.w += __shfl_xor_sync(FULL,a0.w,off);
  }
  int sl = lane>>2;
  float cx = __shfl_sync(FULL,a0.x,sl);
  float cy = __shfl_sync(FULL,a0.y,sl);
  float cz = __shfl_sync(FULL,a0.z,sl);
  float cw = __shfl_sync(FULL,a0.w,sl);
  int c = lane&3;
  return (c==0)?cx:(c==1)?cy:(c==2)?cz:cw;
}

// ======================= CSR build =======================
__global__ void k_zero(){
  int n = blockIdx.x*256 + threadIdx.x;
  if(n<NTOT) g_deg[n]=0;
}
__global__ void k_hist(const int* __restrict__ adj, int E){
  int e = blockIdx.x*256 + threadIdx.x;
  if(e<E) atomicAdd(&g_deg[__ldg(&adj[E+e])], 1);
}
__global__ void k_scanA(){
  __shared__ int sp[SCAN_T];
  int t = threadIdx.x, b = blockIdx.x;
  int i = b*SCAN_T + t;
  int v = (i<NTOT) ? g_deg[i] : 0;
  sp[t]=v; __syncthreads();
  for(int off=1;off<SCAN_T;off<<=1){
    int u = (t>=off)? sp[t-off] : 0;
    __syncthreads();
    sp[t] += u;
    __syncthreads();
  }
  if(i<NTOT) g_scantmp[i]=sp[t];
  if(t==SCAN_T-1) g_bsum[b]=sp[t];
}
// scanC2: each block locally scans the 196 block sums (cheap), then writes
// exclusive row pointers + fill cursors. Replaces scanB+scanC.
__global__ void k_scanC2(){
  __shared__ int sp[256];
  int t = threadIdx.x, b = blockIdx.x;
  if(t<256) sp[t] = (t<SCAN_B) ? g_bsum[t] : 0;
  __syncthreads();
  for(int off=1;off<256;off<<=1){
    int u = (t>=off && t<256) ? sp[t-off] : 0;
    __syncthreads();
    if(t<256) sp[t] += u;
    __syncthreads();
  }
  int boff = (b==0) ? 0 : sp[b-1];
  if(b==0 && t==0) g_rowptr[NTOT] = sp[SCAN_B-1];
  int i = b*SCAN_T + t;
  if(i<NTOT){
    int excl = g_scantmp[i] - g_deg[i] + boff;
    g_rowptr[i]=excl;
    g_fill[i]=excl;
  }
}
__global__ void k_scatter(const int* __restrict__ adj, int E){
  int e = blockIdx.x*256 + threadIdx.x;
  if(e>=E) return;
  int src = __ldg(&adj[e]);
  int dst = __ldg(&adj[E+e]);
  int pos = atomicAdd(&g_fill[dst],1);
  if(pos<EMAX) g_col[pos]=src;
}

// ============ Layer-1 node (THREAD-per-node): z1 = fc1(Xf), s1/d1 ============
__global__ void __launch_bounds__(256,4)
k_node1(const float* __restrict__ X,
        const float* __restrict__ W,    // (32,64) row-major
        const float* __restrict__ bvec,
        const float* __restrict__ aW)   // (64)
{
  __shared__ float4 Wt4[64*8];  // Wt4[k*8+jj] = W[jj*4+c][k]
  __shared__ float  aWs[64];
  __shared__ float4 bs4[8];
  int tid = threadIdx.x;
  for(int i=tid;i<512;i+=256){
    int k=i>>3, jj=i&7;
    Wt4[i] = make_float4(W[(jj*4+0)*64+k], W[(jj*4+1)*64+k],
                         W[(jj*4+2)*64+k], W[(jj*4+3)*64+k]);
  }
  if(tid<64) aWs[tid]=aW[tid];
  if(tid<8)  bs4[tid]=make_float4(bvec[tid*4],bvec[tid*4+1],bvec[tid*4+2],bvec[tid*4+3]);
  __syncthreads();
  int stride = gridDim.x*256;
  for(int n = blockIdx.x*256 + tid; n<NTOT; n+=stride){
    int b = n/NLOC, loc = n-b*NLOC;
    float4 acc[8];
    #pragma unroll
    for(int jj=0;jj<8;jj++) acc[jj]=bs4[jj];
    const float4* Xp = ((const float4*)X) + (size_t)b*TT*NLOC + loc;
    #pragma unroll
    for(int t=0;t<TT;t++){
      float4 xv = __ldg(Xp + (size_t)t*NLOC);
      #pragma unroll
      for(int c=0;c<4;c++){
        float x = (c==0)?xv.x:(c==1)?xv.y:(c==2)?xv.z:xv.w;
        const float4* wr = &Wt4[(t*4+c)*8];
        #pragma unroll
        for(int jj=0;jj<8;jj++){
          float4 w = wr[jj];
          acc[jj].x = fmaf(w.x,x,acc[jj].x);
          acc[jj].y = fmaf(w.y,x,acc[jj].y);
          acc[jj].z = fmaf(w.z,x,acc[jj].z);
          acc[jj].w = fmaf(w.w,x,acc[jj].w);
        }
      }
    }
    float s=0.f, d=0.f;
    #pragma unroll
    for(int jj=0;jj<8;jj++){
      s = fmaf(acc[jj].x,aWs[jj*4+0], fmaf(acc[jj].y,aWs[jj*4+1],
          fmaf(acc[jj].z,aWs[jj*4+2], fmaf(acc[jj].w,aWs[jj*4+3], s))));
      d = fmaf(acc[jj].x,aWs[32+jj*4+0], fmaf(acc[jj].y,aWs[32+jj*4+1],
          fmaf(acc[jj].z,aWs[32+jj*4+2], fmaf(acc[jj].w,aWs[32+jj*4+3], d))));
    }
    float4* zp = ((float4*)g_z1) + (size_t)n*8;
    #pragma unroll
    for(int jj=0;jj<8;jj++) zp[jj]=acc[jj];
    g_s1[n]=s; g_d1[n]=d;
  }
}

// ======== Fused (WARP-per-node, grid-stride): gather1 -> elu -> fc2 -> s2/d2 ========
__global__ void __launch_bounds__(256,5)
k_gat2(const float* __restrict__ W,    // (32,32)
       const float* __restrict__ bvec,
       const float* __restrict__ aW,   // (64)
       const float* __restrict__ att_b1)
{
  __shared__ float Ws[32*32];   // Ws[k*32+j] = W[j][k]  (conflict-free per-k column)
  int tid=threadIdx.x;
  for(int i=tid;i<1024;i+=256){
    int k=i>>5, j=i&31;
    Ws[k*32+j] = W[j*32+k];
  }
  __syncthreads();
  int lane=tid&31, wid=tid>>5;
  float breg = __ldg(&bvec[lane]);
  float aw_s = __ldg(&aW[lane]);
  float aw_d = __ldg(&aW[32+lane]);
  float ab1  = __ldg(att_b1);
  int nWarps = gridDim.x*8;
  int n = blockIdx.x*8 + wid;
  if(n>=NTOT) return;
  int start = __ldg(&g_rowptr[n]);
  int end   = __ldg(&g_rowptr[n+1]);
  float dn  = g_d1[n];
  while(n<NTOT){
    // prefetch next node's descriptors (hides rowptr/d latency behind gather)
    int n2 = n + nWarps;
    int ns=0, ne=0; float dn2=0.f;
    if(n2<NTOT){
      ns = __ldg(&g_rowptr[n2]);
      ne = __ldg(&g_rowptr[n2+1]);
      dn2= __ldg(&g_d1[n2]);
    }
    float acc = gather_row(g_z1, g_s1, start, end, dn+ab1, lane);
    float hin = eluf(acc);
    float z = breg;
    #pragma unroll
    for(int k=0;k<32;k++) z = fmaf(Ws[k*32+lane], __shfl_sync(FULL,hin,k), z);
    // dual warp reduction, interleaved for latency overlap
    float a = z*aw_s, bb = z*aw_d;
    #pragma unroll
    for(int off=16; off; off>>=1){
      a  += __shfl_xor_sync(FULL,a ,off);
      bb += __shfl_xor_sync(FULL,bb,off);
    }
    g_z2[(size_t)n*H+lane]=z;
    if(lane==0){ g_s2[n]=a; g_d2[n]=bb; }
    n=n2; start=ns; end=ne; dn=dn2;
  }
}

// ==== Fused final (WARP-per-node): gather2 -> elu -> GRU -> heads -> SIR -> out ====
__global__ void __launch_bounds__(256,4)
k_final(const float* __restrict__ X,
        const float* __restrict__ states,
        const float* __restrict__ Nvec,
        const float* __restrict__ att_b2,
        const float* __restrict__ Wih,  // (96,32)
        const float* __restrict__ bih,
        const float* __restrict__ bhh,
        const float* __restrict__ WI, const float* __restrict__ bI,
        const float* __restrict__ WR, const float* __restrict__ bR,
        const float* __restrict__ Wsir, const float* __restrict__ bsir,
        float* __restrict__ out)
{
  __shared__ float4 W4[32*32];   // W4[k*32+j] = (Wih_r[j][k], Wih_z[j][k], Wih_n[j][k], 0)
  __shared__ float Wh[18*34];
  __shared__ float bh[18];
  __shared__ float stage[8][32];
  int tid=threadIdx.x;
  for(int i=tid;i<1024;i+=256){
    int k=i>>5, j=i&31;
    W4[i] = make_float4(Wih[j*32+k], Wih[(j+32)*32+k], Wih[(j+64)*32+k], 0.f);
  }
  for(int i=tid;i<8*34;i+=256){ Wh[i]=WI[i]; Wh[8*34+i]=WR[i]; }
  if(tid<2*34) Wh[16*34+tid]=Wsir[tid];
  if(tid<8) bh[tid]=bI[tid];
  else if(tid<16) bh[tid]=bR[tid-8];
  else if(tid<18) bh[tid]=bsir[tid-16];
  __syncthreads();
  int lane=tid&31, wid=tid>>5;
  float bih0=__ldg(&bih[lane]), bih1=__ldg(&bih[32+lane]), bih2=__ldg(&bih[64+lane]);
  float bhh0=__ldg(&bhh[lane]), bhh1=__ldg(&bhh[32+lane]), bhh2=__ldg(&bhh[64+lane]);
  float ab2 = __ldg(att_b2);
  int nWarps = gridDim.x*8;
  int n = blockIdx.x*8 + wid;
  if(n>=NTOT) return;
  int start = __ldg(&g_rowptr[n]);
  int end   = __ldg(&g_rowptr[n+1]);
  float dn  = g_d2[n];
  while(n<NTOT){
    int n2 = n + nWarps;
    int ns=0, ne=0; float dn2=0.f;
    if(n2<NTOT){
      ns = __ldg(&g_rowptr[n2]);
      ne = __ldg(&g_rowptr[n2+1]);
      dn2= __ldg(&g_d2[n2]);
    }
    float acc = gather_row(g_z2, g_s2, start, end, dn+ab2, lane);
    float h2 = eluf(acc);

    float gi0=bih0, gi1=bih1, gi2=bih2;
    #pragma unroll
    for(int k=0;k<32;k++){
      float hv=__shfl_sync(FULL,h2,k);
      float4 w = W4[k*32+lane];
      gi0=fmaf(w.x,hv,gi0);
      gi1=fmaf(w.y,hv,gi1);
      gi2=fmaf(w.z,hv,gi2);
    }
    float r  = sigm(gi0 + bhh0);
    float zg = sigm(gi1 + bhh1);
    float nn = tanhf(gi2 + r*bhh2);
    float hout = (1.f-zg)*nn;

    int b=n/NLOC, loc=n-b*NLOC;
    const float* Xl = X + ((size_t)(b*TT+TT-1)*NLOC + loc)*NFEAT;
    float ldI = __ldg(&Xl[1]), ldR = __ldg(&Xl[2]);

    float hacc = lane<18 ? bh[lane] : 0.f;
    #pragma unroll
    for(int j=0;j<32;j++){
      float hv=__shfl_sync(FULL,hout,j);
      if(lane<18) hacc = fmaf(Wh[lane*34+j],hv,hacc);
    }
    if(lane<18) hacc = fmaf(Wh[lane*34+32],ldI, fmaf(Wh[lane*34+33],ldR,hacc));
    float alpha = sigm(__shfl_sync(FULL, hacc, 16));
    float beta  = sigm(__shfl_sync(FULL, hacc, 17));

    if(lane<8)        stage[wid][2*lane]       = hacc;   // pred_I[h]
    else if(lane<16)  stage[wid][2*(lane-8)+1] = hacc;   // pred_R[h]

    float I  = __ldg(&states[(size_t)n*2]);
    float Rr = __ldg(&states[(size_t)n*2+1]);
    float Nv = __ldg(&Nvec[loc]);
    #pragma unroll
    for(int hh=0;hh<8;hh++){
      float S  = Nv - I - Rr;
      float dI = alpha*I*(S/Nv) - beta*I;
      float dR = beta*I;
      if(lane==16+2*hh) stage[wid][lane]=dI;
      if(lane==17+2*hh) stage[wid][lane]=dR;
      I += dI; Rr += dR;
    }
    __syncwarp();
    float v = stage[wid][lane];
    if(lane<16) out[(size_t)n*16+lane]=v;
    else        out[(size_t)NTOT*16 + (size_t)n*16 + (lane-16)]=v;
    __syncwarp();
    n=n2; start=ns; end=ne; dn=dn2;
  }
}

extern "C" void kernel_launch(void* const* d_in, const int* in_sizes, int n_in,
                              void* d_out, int out_size)
{
  const float* X      = (const float*)d_in[0];
  const int*   adj    = (const int*)d_in[1];     // int32 in practice
  const float* states = (const float*)d_in[2];
  const float* Nvec   = (const float*)d_in[3];
  const float* fc1_W  = (const float*)d_in[4];
  const float* fc1_b  = (const float*)d_in[5];
  const float* att1_W = (const float*)d_in[6];
  const float* att1_b = (const float*)d_in[7];
  const float* fc2_W  = (const float*)d_in[8];
  const float* fc2_b  = (const float*)d_in[9];
  const float* att2_W = (const float*)d_in[10];
  const float* att2_b = (const float*)d_in[11];
  const float* gru_Wih= (const float*)d_in[12];
  /* d_in[13] = gru_Whh: unused (h0 == 0) */
  const float* gru_bih= (const float*)d_in[14];
  const float* gru_bhh= (const float*)d_in[15];
  const float* WI   = (const float*)d_in[16];
  const float* bI   = (const float*)d_in[17];
  const float* WR   = (const float*)d_in[18];
  const float* bR   = (const float*)d_in[19];
  const float* Wsir = (const float*)d_in[20];
  const float* bsir = (const float*)d_in[21];
  float* out = (float*)d_out;

  int E = in_sizes[1]/2;
  int eB = (E+255)/256;
  int nB = (NTOT+255)/256;

  // order: k_node1 at sampled index 3 (verifies the occupancy prediction)
  k_zero   <<<nB,256>>>();
  k_hist   <<<eB,256>>>(adj, E);
  k_scanA  <<<SCAN_B,SCAN_T>>>();
  k_node1  <<<782,256>>>(X, fc1_W, fc1_b, att1_W);   // no CSR dependency
  k_scanC2 <<<SCAN_B,SCAN_T>>>();
  k_scatter<<<eB,256>>>(adj, E);
  k_gat2   <<<1480,256>>>(fc2_W, fc2_b, att2_W, att1_b);
  k_final  <<<1480,256>>>(X, states, Nvec, att2_b, gru_Wih, gru_bih, gru_bhh,
                          WI, bI, WR, bR, Wsir, bsir, out);
}